// round 3
// baseline (speedup 1.0000x reference)
#include <cuda_runtime.h>
#include <math.h>

// inputs [32,64,64,64] NCHW fp32, weight [512,64] fp32.
#define HW_    4096
#define CHW_   262144
#define N_TOK  131072
#define K_     512
#define D_     64

__device__ int   g_enc[N_TOK];
__device__ int   g_counts[K_];
__device__ float g_partials[1024];

// ---- packed fp32x2: two independent IEEE fp32 FMAs per instr (bit-exact per lane) ----
static __device__ __forceinline__ unsigned long long pack2(float lo, float hi) {
    unsigned long long r;
    asm("mov.b64 %0, {%1, %2};" : "=l"(r) : "f"(lo), "f"(hi));
    return r;
}
static __device__ __forceinline__ void unpack2(unsigned long long v, float& lo, float& hi) {
    asm("mov.b64 {%0, %1}, %2;" : "=f"(lo), "=f"(hi) : "l"(v));
}
static __device__ __forceinline__ unsigned long long ffma2(unsigned long long a,
                                                           unsigned long long b,
                                                           unsigned long long c) {
    unsigned long long d;
    asm("fma.rn.f32x2 %0, %1, %2, %3;" : "=l"(d) : "l"(a), "l"(b), "l"(c));
    return d;
}

__global__ void vq_init_kernel() { g_counts[threadIdx.x] = 0; }

// ---------------- argmin kernel ----------------
// smem: interleaved codebook (4 codes per float4 per dim) 128KB | ||w||^2 | histogram
#define SMEM_BYTES (K_ * D_ * 4 + K_ * 4 + K_ * 4)

__global__ __launch_bounds__(256, 1)
void vq_argmin_kernel(const float* __restrict__ input, const float* __restrict__ weight) {
    extern __shared__ float smem[];
    float* sw    = smem;                 // [128 groups][64 d][4 codes] fp32
    float* swn   = smem + K_ * D_;       // [512]
    int*   shist = (int*)(smem + K_ * D_ + K_);

    const int tid = threadIdx.x;

    // interleave codebook: sw[(k>>2)*256 + d*4 + (k&3)] = weight[k][d]
    for (int idx = tid; idx < K_ * D_; idx += 256) {
        int k = idx >> 6, d = idx & 63;
        sw[((k >> 2) << 8) + (d << 2) + (k & 3)] = weight[idx];
    }
    // ||w_k||^2 (order-insensitive: magnitude ~1e-7 << fp32 grid of distances)
    for (int k = tid; k < K_; k += 256) {
        const float* wr = weight + (k << 6);
        float c = 0.f;
        #pragma unroll
        for (int d = 0; d < 64; d++) c = __fadd_rn(c, __fmul_rn(wr[d], wr[d]));
        swn[k] = c;
    }
    shist[tid] = 0; shist[tid + 256] = 0;
    __syncthreads();

    // one token per thread
    const int token = blockIdx.x * 256 + tid;
    const float* ip = input + ((token >> 12) << 18) + (token & (HW_ - 1));

    float x[64];
    #pragma unroll
    for (int d = 0; d < 64; d++) x[d] = __ldg(ip + d * HW_);

    // A = ||x||^2 replicating XLA-GPU warp row-reduce:
    // leaves p_t = fl(x[2t]^2 + x[2t+1]^2), then butterfly tree offsets 16,8,4,2,1
    float p[32];
    #pragma unroll
    for (int t = 0; t < 32; t++)
        p[t] = __fadd_rn(__fmul_rn(x[2 * t], x[2 * t]),
                         __fmul_rn(x[2 * t + 1], x[2 * t + 1]));
    float q[16], r[8], s[4], u[2];
    #pragma unroll
    for (int t = 0; t < 16; t++) q[t] = __fadd_rn(p[t], p[t + 16]);
    #pragma unroll
    for (int t = 0; t < 8; t++)  r[t] = __fadd_rn(q[t], q[t + 8]);
    #pragma unroll
    for (int t = 0; t < 4; t++)  s[t] = __fadd_rn(r[t], r[t + 4]);
    #pragma unroll
    for (int t = 0; t < 2; t++)  u[t] = __fadd_rn(s[t], s[t + 2]);
    const float A = __fadd_rn(u[0], u[1]);

    float best  = INFINITY;
    int   bestk = 0;

    // 16 codes per tile (4 interleave groups); dot = sequential ascending-d FFMA chain
    // per code (cublas sgemm order), two codes per f32x2 lane-pair.
    #pragma unroll 1
    for (int g0 = 0; g0 < 128; g0 += 4) {
        const ulonglong2* w0 = (const ulonglong2*)(sw + ((g0 + 0) << 8));
        const ulonglong2* w1 = (const ulonglong2*)(sw + ((g0 + 1) << 8));
        const ulonglong2* w2 = (const ulonglong2*)(sw + ((g0 + 2) << 8));
        const ulonglong2* w3 = (const ulonglong2*)(sw + ((g0 + 3) << 8));
        unsigned long long a0 = 0, a1 = 0, a2 = 0, a3 = 0, a4 = 0, a5 = 0, a6 = 0, a7 = 0;
        #pragma unroll
        for (int d = 0; d < 64; d++) {
            unsigned long long px = pack2(x[d], x[d]);
            ulonglong2 v0 = w0[d]; a0 = ffma2(px, v0.x, a0); a1 = ffma2(px, v0.y, a1);
            ulonglong2 v1 = w1[d]; a2 = ffma2(px, v1.x, a2); a3 = ffma2(px, v1.y, a3);
            ulonglong2 v2 = w2[d]; a4 = ffma2(px, v2.x, a4); a5 = ffma2(px, v2.y, a5);
            ulonglong2 v3 = w3[d]; a6 = ffma2(px, v3.x, a6); a7 = ffma2(px, v3.y, a7);
        }
        unsigned long long acc[8] = {a0, a1, a2, a3, a4, a5, a6, a7};
        #pragma unroll
        for (int j = 0; j < 8; j++) {
            float lo, hi;
            unpack2(acc[j], lo, hi);
            const int k = (g0 << 2) + (j << 1);
            // dist = fl( fl(A - 2*dot) + C )  — reference association
            float m0 = __fmul_rn(2.0f, lo);
            float d0 = __fadd_rn(__fadd_rn(A, -m0), swn[k]);
            if (d0 < best) { best = d0; bestk = k; }
            float m1 = __fmul_rn(2.0f, hi);
            float d1 = __fadd_rn(__fadd_rn(A, -m1), swn[k + 1]);
            if (d1 < best) { best = d1; bestk = k + 1; }
        }
    }

    g_enc[token] = bestk;
    atomicAdd(&shist[bestk], 1);
    __syncthreads();
    if (shist[tid])       atomicAdd(&g_counts[tid],       shist[tid]);
    if (shist[tid + 256]) atomicAdd(&g_counts[tid + 256], shist[tid + 256]);
}

// ---------------- gather + straight-through + MSE partials ----------------
__global__ __launch_bounds__(256)
void vq_gather_kernel(const float* __restrict__ input, const float* __restrict__ weight,
                      float* __restrict__ out, int nq4) {
    __shared__ float red[256];
    const float4* in4  = (const float4*)input;
    const float4* w4   = (const float4*)weight;
    float4*       out4 = (float4*)out;

    float local = 0.f;
    const int stride = gridDim.x * blockDim.x;
    for (int j = blockIdx.x * blockDim.x + threadIdx.x; j < nq4; j += stride) {
        const int token = j >> 4;
        const int d4    = j & 15;
        const int k     = g_enc[token];
        float4 qv = w4[k * 16 + d4];
        float4 xv = in4[j];
        // t = fl(q - x); out = fl(x + t)  (replicates straight-through arithmetic)
        float t0 = __fadd_rn(qv.x, -xv.x);
        float t1 = __fadd_rn(qv.y, -xv.y);
        float t2 = __fadd_rn(qv.z, -xv.z);
        float t3 = __fadd_rn(qv.w, -xv.w);
        float4 ov;
        ov.x = __fadd_rn(xv.x, t0);
        ov.y = __fadd_rn(xv.y, t1);
        ov.z = __fadd_rn(xv.z, t2);
        ov.w = __fadd_rn(xv.w, t3);
        out4[j] = ov;
        local += t0 * t0 + t1 * t1 + t2 * t2 + t3 * t3;
    }
    red[threadIdx.x] = local;
    __syncthreads();
    #pragma unroll
    for (int sft = 128; sft > 0; sft >>= 1) {
        if (threadIdx.x < sft) red[threadIdx.x] += red[threadIdx.x + sft];
        __syncthreads();
    }
    if (threadIdx.x == 0) g_partials[blockIdx.x] = red[0];
}

// ---------------- final: loss + perplexity ----------------
__global__ __launch_bounds__(512)
void vq_final_kernel(float* __restrict__ out, int nq, float inv_nq) {
    __shared__ float  red[512];
    __shared__ double redd[512];
    const int t = threadIdx.x;

    red[t] = g_partials[t] + g_partials[t + 512];
    __syncthreads();
    #pragma unroll
    for (int sft = 256; sft > 0; sft >>= 1) {
        if (t < sft) red[t] += red[t + sft];
        __syncthreads();
    }
    const float loss = 1.25f * red[0] * inv_nq;   // q_loss + 0.25*e_loss, identical terms
    __syncthreads();

    // p = counts / 131072 (exact: *2^-17); term = p * log(p + 1e-10)
    const float pf = (float)g_counts[t] * (1.0f / (float)N_TOK);
    const float sf = __fadd_rn(pf, 1e-10f);
    redd[t] = (double)pf * log((double)sf);
    __syncthreads();
    #pragma unroll
    for (int sft = 256; sft > 0; sft >>= 1) {
        if (t < sft) redd[t] += redd[t + sft];
        __syncthreads();
    }
    if (t == 0) {
        out[nq]     = loss;
        out[nq + 1] = (float)exp(-redd[0]);
    }
}

extern "C" void kernel_launch(void* const* d_in, const int* in_sizes, int n_in,
                              void* d_out, int out_size) {
    const float* input  = (const float*)d_in[0];
    const float* weight = (const float*)d_in[1];
    float*       out    = (float*)d_out;

    const int nq = out_size - 2;

    cudaFuncSetAttribute(vq_argmin_kernel,
                         cudaFuncAttributeMaxDynamicSharedMemorySize, SMEM_BYTES);

    vq_init_kernel<<<1, K_>>>();
    vq_argmin_kernel<<<N_TOK / 256, 256, SMEM_BYTES>>>(input, weight);
    vq_gather_kernel<<<1024, 256>>>(input, weight, out, nq / 4);
    vq_final_kernel<<<1, 512>>>(out, nq, 1.0f / (float)nq);
}

// round 5
// speedup vs baseline: 1.1800x; 1.1800x over previous
#include <cuda_runtime.h>
#include <math.h>

// inputs [32,64,64,64] NCHW fp32, weight [512,64] fp32.
#define HW_    4096
#define CHW_   262144
#define N_TOK  131072
#define K_     512
#define D_     64

__device__ int   g_enc[N_TOK];
__device__ int   g_counts[K_];
__device__ float g_partials[1024];

// ---- packed fp32x2: two independent IEEE fp32 FMAs per instr (bit-exact per lane) ----
static __device__ __forceinline__ unsigned long long pack2(float lo, float hi) {
    unsigned long long r;
    asm("mov.b64 %0, {%1, %2};" : "=l"(r) : "f"(lo), "f"(hi));
    return r;
}
static __device__ __forceinline__ void unpack2(unsigned long long v, float& lo, float& hi) {
    asm("mov.b64 {%0, %1}, %2;" : "=f"(lo), "=f"(hi) : "l"(v));
}
static __device__ __forceinline__ unsigned long long ffma2(unsigned long long a,
                                                           unsigned long long b,
                                                           unsigned long long c) {
    unsigned long long d;
    asm("fma.rn.f32x2 %0, %1, %2, %3;" : "=l"(d) : "l"(a), "l"(b), "l"(c));
    return d;
}

__global__ void vq_init_kernel() { g_counts[threadIdx.x] = 0; }

// ---------------- argmin kernel ----------------
// smem: interleaved codebook (4 codes per float4 per dim) 128KB | ||w||^2 | histogram
#define SMEM_BYTES (K_ * D_ * 4 + K_ * 4 + K_ * 4)

__global__ __launch_bounds__(512, 1)
void vq_argmin_kernel(const float* __restrict__ input, const float* __restrict__ weight) {
    extern __shared__ float smem[];
    float* sw    = smem;                 // [128 groups][64 d][4 codes] fp32
    float* swn   = smem + K_ * D_;       // [512]
    int*   shist = (int*)(smem + K_ * D_ + K_);

    const int tid = threadIdx.x;

    // interleave codebook: sw[(k>>2)*256 + d*4 + (k&3)] = weight[k][d]
    for (int idx = tid; idx < K_ * D_; idx += 512) {
        int k = idx >> 6, d = idx & 63;
        sw[((k >> 2) << 8) + (d << 2) + (k & 3)] = weight[idx];
    }
    // ||w_k||^2 : ascending-d chain (validated; magnitude << fp32 distance grid)
    {
        const float* wr = weight + (tid << 6);
        float c = 0.f;
        #pragma unroll
        for (int d = 0; d < 64; d++) c = __fadd_rn(c, __fmul_rn(wr[d], wr[d]));
        swn[tid] = c;
    }
    shist[tid] = 0;
    __syncthreads();

    // one token per thread
    const int token = blockIdx.x * 512 + tid;
    const float* ip = input + ((token >> 12) << 18) + (token & (HW_ - 1));

    float x[64];
    #pragma unroll
    for (int d = 0; d < 64; d++) x[d] = __ldg(ip + d * HW_);

    // A = ||x||^2 replicating XLA-GPU warp row-reduce (validated):
    // leaves p_t = fl(x[2t]^2 + x[2t+1]^2), then butterfly offsets 16,8,4,2,1
    float p[32];
    #pragma unroll
    for (int t = 0; t < 32; t++)
        p[t] = __fadd_rn(__fmul_rn(x[2 * t], x[2 * t]),
                         __fmul_rn(x[2 * t + 1], x[2 * t + 1]));
    float qv[16], rv[8], sv[4], uv[2];
    #pragma unroll
    for (int t = 0; t < 16; t++) qv[t] = __fadd_rn(p[t], p[t + 16]);
    #pragma unroll
    for (int t = 0; t < 8; t++)  rv[t] = __fadd_rn(qv[t], qv[t + 8]);
    #pragma unroll
    for (int t = 0; t < 4; t++)  sv[t] = __fadd_rn(rv[t], rv[t + 4]);
    #pragma unroll
    for (int t = 0; t < 2; t++)  uv[t] = __fadd_rn(sv[t], sv[t + 2]);
    const float A = __fadd_rn(uv[0], uv[1]);

    float best  = INFINITY;
    int   bestk = 0;

    // 8 codes per tile (2 interleave groups): 4 f32x2 accumulators -> low reg
    // pressure so 512 threads fit 128 regs with no spills. Per-code dot is the
    // same sequential ascending-d FFMA chain as the validated kernel.
    #pragma unroll 1
    for (int g0 = 0; g0 < 128; g0 += 2) {
        const ulonglong2* w0 = (const ulonglong2*)(sw + ((g0 + 0) << 8));
        const ulonglong2* w1 = (const ulonglong2*)(sw + ((g0 + 1) << 8));
        unsigned long long a0 = 0, a1 = 0, a2 = 0, a3 = 0;
        #pragma unroll
        for (int d = 0; d < 64; d++) {
            unsigned long long px = pack2(x[d], x[d]);
            ulonglong2 v0 = w0[d]; a0 = ffma2(px, v0.x, a0); a1 = ffma2(px, v0.y, a1);
            ulonglong2 v1 = w1[d]; a2 = ffma2(px, v1.x, a2); a3 = ffma2(px, v1.y, a3);
        }
        unsigned long long acc[4] = {a0, a1, a2, a3};
        #pragma unroll
        for (int j = 0; j < 4; j++) {
            float lo, hi;
            unpack2(acc[j], lo, hi);
            const int k = (g0 << 2) + (j << 1);
            // dist = fl( fl(A - 2*dot) + C )  — reference association (validated)
            float m0 = __fmul_rn(2.0f, lo);
            float d0 = __fadd_rn(__fadd_rn(A, -m0), swn[k]);
            if (d0 < best) { best = d0; bestk = k; }
            float m1 = __fmul_rn(2.0f, hi);
            float d1 = __fadd_rn(__fadd_rn(A, -m1), swn[k + 1]);
            if (d1 < best) { best = d1; bestk = k + 1; }
        }
    }

    g_enc[token] = bestk;
    atomicAdd(&shist[bestk], 1);
    __syncthreads();
    if (shist[tid]) atomicAdd(&g_counts[tid], shist[tid]);
}

// ---------------- gather + straight-through + MSE partials ----------------
__global__ __launch_bounds__(256)
void vq_gather_kernel(const float* __restrict__ input, const float* __restrict__ weight,
                      float* __restrict__ out, int nq4) {
    __shared__ float red[256];
    const float4* in4  = (const float4*)input;
    const float4* w4   = (const float4*)weight;
    float4*       out4 = (float4*)out;

    float local = 0.f;
    const int stride = gridDim.x * blockDim.x;
    for (int j = blockIdx.x * blockDim.x + threadIdx.x; j < nq4; j += stride) {
        const int token = j >> 4;
        const int d4    = j & 15;
        const int k     = g_enc[token];
        float4 qv = w4[k * 16 + d4];
        float4 xv = in4[j];
        // t = fl(q - x); out = fl(x + t)  (straight-through arithmetic, validated)
        float t0 = __fadd_rn(qv.x, -xv.x);
        float t1 = __fadd_rn(qv.y, -xv.y);
        float t2 = __fadd_rn(qv.z, -xv.z);
        float t3 = __fadd_rn(qv.w, -xv.w);
        float4 ov;
        ov.x = __fadd_rn(xv.x, t0);
        ov.y = __fadd_rn(xv.y, t1);
        ov.z = __fadd_rn(xv.z, t2);
        ov.w = __fadd_rn(xv.w, t3);
        out4[j] = ov;
        local += t0 * t0 + t1 * t1 + t2 * t2 + t3 * t3;
    }
    red[threadIdx.x] = local;
    __syncthreads();
    #pragma unroll
    for (int sft = 128; sft > 0; sft >>= 1) {
        if (threadIdx.x < sft) red[threadIdx.x] += red[threadIdx.x + sft];
        __syncthreads();
    }
    if (threadIdx.x == 0) g_partials[blockIdx.x] = red[0];
}

// ---------------- final: loss + perplexity (fp32 MUFU path) ----------------
__global__ __launch_bounds__(512)
void vq_final_kernel(float* __restrict__ out, int nq, float inv_nq) {
    __shared__ float red[512];
    const int t = threadIdx.x;

    red[t] = g_partials[t] + g_partials[t + 512];
    __syncthreads();
    #pragma unroll
    for (int sft = 256; sft > 0; sft >>= 1) {
        if (t < sft) red[t] += red[t + sft];
        __syncthreads();
    }
    const float loss = 1.25f * red[0] * inv_nq;   // q_loss + 0.25*e_loss, identical terms
    __syncthreads();

    // p = counts * 2^-17 (exact); entropy term in fp32 via MUFU (error << 1e-3 budget)
    const float pf = (float)g_counts[t] * (1.0f / (float)N_TOK);
    red[t] = pf * __logf(__fadd_rn(pf, 1e-10f));
    __syncthreads();
    #pragma unroll
    for (int sft = 256; sft > 0; sft >>= 1) {
        if (t < sft) red[t] += red[t + sft];
        __syncthreads();
    }
    if (t == 0) {
        out[nq]     = loss;
        out[nq + 1] = __expf(-red[0]);
    }
}

extern "C" void kernel_launch(void* const* d_in, const int* in_sizes, int n_in,
                              void* d_out, int out_size) {
    const float* input  = (const float*)d_in[0];
    const float* weight = (const float*)d_in[1];
    float*       out    = (float*)d_out;

    const int nq = out_size - 2;

    cudaFuncSetAttribute(vq_argmin_kernel,
                         cudaFuncAttributeMaxDynamicSharedMemorySize, SMEM_BYTES);

    vq_init_kernel<<<1, K_>>>();
    vq_argmin_kernel<<<N_TOK / 512, 512, SMEM_BYTES>>>(input, weight);
    vq_gather_kernel<<<1024, 256>>>(input, weight, out, nq / 4);
    vq_final_kernel<<<1, 512>>>(out, nq, 1.0f / (float)nq);
}